// round 7
// baseline (speedup 1.0000x reference)
#include <cuda_runtime.h>
#include <cuda_bf16.h>

// Problem constants (fixed by the reference)
static constexpr int BN = 262144;   // batch (2^18)
static constexpr int KN = 3;        // centers per class
static constexpr int DN = 64;       // feature dim
static constexpr int CBINS = 1024;  // >= num_classes (1000), power of 2
static constexpr float TH_F  = 1e0f * 0.95f;
static constexpr float EPS_F = 1e-12f;

static constexpr int GRID   = 2048;                 // dist kernel: 16384 warps
static constexpr int NWARPS = GRID * 256 / 32;      // 16384
static constexpr int ITERS  = BN / 4 / NWARPS;      // 4 row-groups per warp

// ---- Device scratch (no allocs allowed) ----
__device__ int g_hist[CBINS];     // zero-init at load; re-zeroed by scatter each run
__device__ int g_offset[CBINS];   // rewritten by scan each run
__device__ int g_sorted[BN];      // packed (label<<18 | row), label-sorted

// Global accumulators (reset by dist's last block each run)
__device__ double g_sum_min    = 0.0;
__device__ double g_sum_masked = 0.0;
__device__ double g_cnt        = 0.0;
__device__ unsigned int g_done = 0u;

// ---------------- Phase 1: histogram of labels ----------------
__global__ void __launch_bounds__(256)
hist_kernel(const int* __restrict__ labels)
{
    __shared__ int sh[CBINS];
    for (int i = threadIdx.x; i < CBINS; i += 256) sh[i] = 0;
    __syncthreads();

    const int tid = blockIdx.x * 256 + threadIdx.x;
    const int stride = gridDim.x * 256;
    for (int i = tid; i < BN; i += stride)
        atomicAdd(&sh[__ldg(&labels[i])], 1);
    __syncthreads();

    for (int i = threadIdx.x; i < CBINS; i += 256) {
        const int v = sh[i];
        if (v) atomicAdd(&g_hist[i], v);
    }
}

// ---------------- Phase 2: exclusive scan over bins ----------------
__global__ void __launch_bounds__(1024)
scan_kernel()
{
    __shared__ int warp_sums[32];
    const int tid  = threadIdx.x;
    const int lane = tid & 31;
    const int wid  = tid >> 5;

    const int v = g_hist[tid];
    int x = v;
    #pragma unroll
    for (int o = 1; o < 32; o <<= 1) {
        const int y = __shfl_up_sync(0xffffffffu, x, o);
        if (lane >= o) x += y;
    }
    if (lane == 31) warp_sums[wid] = x;
    __syncthreads();
    if (wid == 0) {
        int s = warp_sums[lane];
        #pragma unroll
        for (int o = 1; o < 32; o <<= 1) {
            const int y = __shfl_up_sync(0xffffffffu, s, o);
            if (lane >= o) s += y;
        }
        warp_sums[lane] = s;
    }
    __syncthreads();

    g_offset[tid] = x - v + (wid ? warp_sums[wid - 1] : 0);
}

// ---------------- Phase 3: scatter rows into label-sorted order ----------------
__global__ void __launch_bounds__(256)
scatter_kernel(const int* __restrict__ labels)
{
    // Re-zero the histogram for the NEXT run (scan already consumed it)
    if (blockIdx.x == 0)
        for (int i = threadIdx.x; i < CBINS; i += 256) g_hist[i] = 0;

    const int tid = blockIdx.x * 256 + threadIdx.x;
    const int stride = gridDim.x * 256;
    for (int i = tid; i < BN; i += stride) {
        const int lab = __ldg(&labels[i]);
        const int pos = atomicAdd(&g_offset[lab], 1);
        g_sorted[pos] = (lab << 18) | i;   // BN = 2^18, row fits in 18 bits
    }
}

// ---------------- Phase 4: distances over sorted rows ----------------
__device__ __forceinline__ float dist4(const float4 a, const float4 b) {
    const float d0 = a.x - b.x, d1 = a.y - b.y;
    const float d2 = a.z - b.z, d3 = a.w - b.w;
    return d0 * d0 + d1 * d1 + d2 * d2 + d3 * d3;
}

// 8 lanes per row, 4 rows per warp-iteration, 4 iterations per warp.
// Rows come from g_sorted: consecutive sorted positions share a label, so the
// center loads hit L1/L2 on the same 768B -> center L2 traffic ~ eliminated.
__global__ void __launch_bounds__(256)
dist_kernel(const float4* __restrict__ x4,
            const float4* __restrict__ c4,
            float*        __restrict__ out)
{
    const int lane    = threadIdx.x & 31;
    const int r       = lane >> 3;       // row within group (0..3)
    const int s       = lane & 7;        // float4 slot within 128B half-row
    const int warp_id = (blockIdx.x * blockDim.x + threadIdx.x) >> 5;

    // Prefetch packed (label, row) for all iterations (16B contiguous per group)
    int packed[ITERS];
    #pragma unroll
    for (int it = 0; it < ITERS; it++) {
        const int sp = (warp_id + it * NWARPS) * 4 + r;   // sorted position
        packed[it] = __ldg(&g_sorted[sp]);
    }

    float acc_min = 0.f, acc_msk = 0.f, acc_cnt = 0.f;

    #pragma unroll
    for (int it = 0; it < ITERS; it++) {
        const int row = packed[it] & (BN - 1);
        const int lab = packed[it] >> 18;

        // x: random 256B row gather; dense 128B lines per lane pair.
        // __ldcs keeps the (unreusable) x stream from evicting hot centers in L1.
        const float4* xb = x4 + (size_t)row * 16 + s;
        const float4 xv0 = __ldcs(xb + 0);
        const float4 xv1 = __ldcs(xb + 8);

        const float4* cb = c4 + (size_t)lab * (KN * (DN / 4)) + s;

        // 3 centers x 2 half-rows; same label across group/warp -> L1 hits
        const float4 c00 = __ldg(cb + 0);
        const float4 c01 = __ldg(cb + 8);
        const float4 c10 = __ldg(cb + 16);
        const float4 c11 = __ldg(cb + 24);
        const float4 c20 = __ldg(cb + 32);
        const float4 c21 = __ldg(cb + 40);

        float p0 = dist4(xv0, c00) + dist4(xv1, c01);
        float p1 = dist4(xv0, c10) + dist4(xv1, c11);
        float p2 = dist4(xv0, c20) + dist4(xv1, c21);

        // Reduce within the 8-lane group (xor 1,2,4 never crosses groups)
        #pragma unroll
        for (int o = 1; o < 8; o <<= 1) {
            p0 += __shfl_xor_sync(0xffffffffu, p0, o);
            p1 += __shfl_xor_sync(0xffffffffu, p1, o);
            p2 += __shfl_xor_sync(0xffffffffu, p2, o);
        }

        if (s == 0) {
            const float mn  = fminf(fminf(p0, p1), p2);
            const float mx  = fmaxf(fmaxf(p0, p1), p2);
            const float mid = (p0 + p1 + p2) - mn - mx;

            const float a = mn  + EPS_F;
            const float b = mid + EPS_F;
            const float p = a / (a + b);                  // 0 < p <= 0.5
            const float ent = -(p * log2f(p) + (1.f - p) * log2f(1.f - p));

            acc_min += mn;
            if (ent <= TH_F) { acc_msk += mn; acc_cnt += 1.f; }
        }
    }

    // Warp reduce (only s==0 lanes carry nonzero values)
    #pragma unroll
    for (int o = 16; o > 0; o >>= 1) {
        acc_min += __shfl_xor_sync(0xffffffffu, acc_min, o);
        acc_msk += __shfl_xor_sync(0xffffffffu, acc_msk, o);
        acc_cnt += __shfl_xor_sync(0xffffffffu, acc_cnt, o);
    }

    // Block reduce + one double atomic triple per block
    __shared__ float sm[3][8];
    __shared__ bool  s_last;
    const int wib = threadIdx.x >> 5;
    if (lane == 0) { sm[0][wib] = acc_min; sm[1][wib] = acc_msk; sm[2][wib] = acc_cnt; }
    __syncthreads();

    if (threadIdx.x == 0) {
        float a = 0.f, b = 0.f, c = 0.f;
        #pragma unroll
        for (int i = 0; i < 8; i++) { a += sm[0][i]; b += sm[1][i]; c += sm[2][i]; }
        atomicAdd(&g_sum_min,    (double)a);
        atomicAdd(&g_sum_masked, (double)b);
        atomicAdd(&g_cnt,        (double)c);
        __threadfence();
        const unsigned int ticket = atomicAdd(&g_done, 1u);
        s_last = (ticket == (unsigned int)(GRID - 1));
    }
    __syncthreads();

    // Last block: produce outputs and reset accumulators for the next replay
    if (s_last && threadIdx.x == 0) {
        __threadfence();
        const double smn = g_sum_min;
        const double smk = g_sum_masked;
        const double cnt = g_cnt;
        out[0] = (float)(smn / (double)BN);
        out[1] = (float)(smk / cnt);
        g_sum_min = 0.0; g_sum_masked = 0.0; g_cnt = 0.0;
        __threadfence();
        g_done = 0u;
    }
}

extern "C" void kernel_launch(void* const* d_in, const int* in_sizes, int n_in,
                              void* d_out, int out_size) {
    const float* x       = (const float*)d_in[0];   // [B, D] f32
    const int*   labels  = (const int*)  d_in[1];   // [B] i32
    const float* centers = (const float*)d_in[2];   // [C, K, D] f32

    hist_kernel<<<256, 256>>>(labels);
    scan_kernel<<<1, 1024>>>();
    scatter_kernel<<<512, 256>>>(labels);
    dist_kernel<<<GRID, 256>>>((const float4*)x, (const float4*)centers, (float*)d_out);
}

// round 8
// speedup vs baseline: 1.0316x; 1.0316x over previous
#include <cuda_runtime.h>
#include <cuda_bf16.h>

// Problem constants (fixed by the reference)
static constexpr int BN = 262144;   // batch (2^18)
static constexpr int KN = 3;        // centers per class
static constexpr int DN = 64;       // feature dim
static constexpr int CBINS = 1024;  // >= num_classes (1000), power of 2
static constexpr float TH_F  = 1e0f * 0.95f;
static constexpr float EPS_F = 1e-12f;

static constexpr int GRID   = 2048;                 // dist kernel: 16384 warps
static constexpr int NWARPS = GRID * 256 / 32;      // 16384
static constexpr int ITERS  = BN / 4 / NWARPS;      // 4 row-groups per warp

// ---- Device scratch (no allocs allowed) ----
__device__ int g_hist[CBINS];     // zero-init at load; re-zeroed by scatter each run
__device__ int g_offset[CBINS];   // rewritten by scan each run
__device__ int g_sorted[BN];      // packed (label<<18 | row), label-sorted

// Global accumulators (reset by dist's last block each run)
__device__ double g_sum_min    = 0.0;
__device__ double g_sum_masked = 0.0;
__device__ double g_cnt        = 0.0;
__device__ unsigned int g_done = 0u;

// ---------------- Phase 1: histogram of labels ----------------
__global__ void __launch_bounds__(256)
hist_kernel(const int* __restrict__ labels)
{
    __shared__ int sh[CBINS];
    for (int i = threadIdx.x; i < CBINS; i += 256) sh[i] = 0;
    __syncthreads();

    const int tid = blockIdx.x * 256 + threadIdx.x;
    const int stride = gridDim.x * 256;
    for (int i = tid; i < BN; i += stride)
        atomicAdd(&sh[__ldg(&labels[i])], 1);
    __syncthreads();

    for (int i = threadIdx.x; i < CBINS; i += 256) {
        const int v = sh[i];
        if (v) atomicAdd(&g_hist[i], v);
    }
}

// ---------------- Phase 2: exclusive scan over bins ----------------
__global__ void __launch_bounds__(1024)
scan_kernel()
{
    __shared__ int warp_sums[32];
    const int tid  = threadIdx.x;
    const int lane = tid & 31;
    const int wid  = tid >> 5;

    const int v = g_hist[tid];
    int x = v;
    #pragma unroll
    for (int o = 1; o < 32; o <<= 1) {
        const int y = __shfl_up_sync(0xffffffffu, x, o);
        if (lane >= o) x += y;
    }
    if (lane == 31) warp_sums[wid] = x;
    __syncthreads();
    if (wid == 0) {
        int s = warp_sums[lane];
        #pragma unroll
        for (int o = 1; o < 32; o <<= 1) {
            const int y = __shfl_up_sync(0xffffffffu, s, o);
            if (lane >= o) s += y;
        }
        warp_sums[lane] = s;
    }
    __syncthreads();

    g_offset[tid] = x - v + (wid ? warp_sums[wid - 1] : 0);
}

// ---------------- Phase 3: scatter rows into label-sorted order ----------------
__global__ void __launch_bounds__(256)
scatter_kernel(const int* __restrict__ labels)
{
    // Re-zero the histogram for the NEXT run (scan already consumed it)
    if (blockIdx.x == 0)
        for (int i = threadIdx.x; i < CBINS; i += 256) g_hist[i] = 0;

    const int tid = blockIdx.x * 256 + threadIdx.x;
    const int stride = gridDim.x * 256;
    for (int i = tid; i < BN; i += stride) {
        const int lab = __ldg(&labels[i]);
        const int pos = atomicAdd(&g_offset[lab], 1);
        g_sorted[pos] = (lab << 18) | i;   // BN = 2^18, row fits in 18 bits
    }
}

// ---------------- Phase 4: distances over sorted rows ----------------
__device__ __forceinline__ float dist4(const float4 a, const float4 b) {
    const float d0 = a.x - b.x, d1 = a.y - b.y;
    const float d2 = a.z - b.z, d3 = a.w - b.w;
    return d0 * d0 + d1 * d1 + d2 * d2 + d3 * d3;
}

// 8 lanes per row, 4 rows per warp-iteration, 4 iterations per warp.
// Rows come from g_sorted: consecutive sorted positions share a label, so the
// center loads hit L1/L2 on the same 768B -> center L2 traffic ~ eliminated.
__global__ void __launch_bounds__(256)
dist_kernel(const float4* __restrict__ x4,
            const float4* __restrict__ c4,
            float*        __restrict__ out)
{
    const int lane    = threadIdx.x & 31;
    const int r       = lane >> 3;       // row within group (0..3)
    const int s       = lane & 7;        // float4 slot within 128B half-row
    const int warp_id = (blockIdx.x * blockDim.x + threadIdx.x) >> 5;

    // Prefetch packed (label, row) for all iterations (16B contiguous per group)
    int packed[ITERS];
    #pragma unroll
    for (int it = 0; it < ITERS; it++) {
        const int sp = (warp_id + it * NWARPS) * 4 + r;   // sorted position
        packed[it] = __ldg(&g_sorted[sp]);
    }

    float acc_min = 0.f, acc_msk = 0.f, acc_cnt = 0.f;

    #pragma unroll
    for (int it = 0; it < ITERS; it++) {
        const int row = packed[it] & (BN - 1);
        const int lab = packed[it] >> 18;

        // x: random 256B row gather; dense 128B lines per lane pair.
        // __ldcs keeps the (unreusable) x stream from evicting hot centers in L1.
        const float4* xb = x4 + (size_t)row * 16 + s;
        const float4 xv0 = __ldcs(xb + 0);
        const float4 xv1 = __ldcs(xb + 8);

        const float4* cb = c4 + (size_t)lab * (KN * (DN / 4)) + s;

        // 3 centers x 2 half-rows; same label across group/warp -> L1 hits
        const float4 c00 = __ldg(cb + 0);
        const float4 c01 = __ldg(cb + 8);
        const float4 c10 = __ldg(cb + 16);
        const float4 c11 = __ldg(cb + 24);
        const float4 c20 = __ldg(cb + 32);
        const float4 c21 = __ldg(cb + 40);

        float p0 = dist4(xv0, c00) + dist4(xv1, c01);
        float p1 = dist4(xv0, c10) + dist4(xv1, c11);
        float p2 = dist4(xv0, c20) + dist4(xv1, c21);

        // Reduce within the 8-lane group (xor 1,2,4 never crosses groups)
        #pragma unroll
        for (int o = 1; o < 8; o <<= 1) {
            p0 += __shfl_xor_sync(0xffffffffu, p0, o);
            p1 += __shfl_xor_sync(0xffffffffu, p1, o);
            p2 += __shfl_xor_sync(0xffffffffu, p2, o);
        }

        if (s == 0) {
            const float mn  = fminf(fminf(p0, p1), p2);
            const float mx  = fmaxf(fmaxf(p0, p1), p2);
            const float mid = (p0 + p1 + p2) - mn - mx;

            const float a = mn  + EPS_F;
            const float b = mid + EPS_F;
            const float p = a / (a + b);                  // 0 < p <= 0.5
            const float ent = -(p * log2f(p) + (1.f - p) * log2f(1.f - p));

            acc_min += mn;
            if (ent <= TH_F) { acc_msk += mn; acc_cnt += 1.f; }
        }
    }

    // Warp reduce (only s==0 lanes carry nonzero values)
    #pragma unroll
    for (int o = 16; o > 0; o >>= 1) {
        acc_min += __shfl_xor_sync(0xffffffffu, acc_min, o);
        acc_msk += __shfl_xor_sync(0xffffffffu, acc_msk, o);
        acc_cnt += __shfl_xor_sync(0xffffffffu, acc_cnt, o);
    }

    // Block reduce + one double atomic triple per block
    __shared__ float sm[3][8];
    __shared__ bool  s_last;
    const int wib = threadIdx.x >> 5;
    if (lane == 0) { sm[0][wib] = acc_min; sm[1][wib] = acc_msk; sm[2][wib] = acc_cnt; }
    __syncthreads();

    if (threadIdx.x == 0) {
        float a = 0.f, b = 0.f, c = 0.f;
        #pragma unroll
        for (int i = 0; i < 8; i++) { a += sm[0][i]; b += sm[1][i]; c += sm[2][i]; }
        atomicAdd(&g_sum_min,    (double)a);
        atomicAdd(&g_sum_masked, (double)b);
        atomicAdd(&g_cnt,        (double)c);
        __threadfence();
        const unsigned int ticket = atomicAdd(&g_done, 1u);
        s_last = (ticket == (unsigned int)(GRID - 1));
    }
    __syncthreads();

    // Last block: produce outputs and reset accumulators for the next replay
    if (s_last && threadIdx.x == 0) {
        __threadfence();
        const double smn = g_sum_min;
        const double smk = g_sum_masked;
        const double cnt = g_cnt;
        out[0] = (float)(smn / (double)BN);
        out[1] = (float)(smk / cnt);
        g_sum_min = 0.0; g_sum_masked = 0.0; g_cnt = 0.0;
        __threadfence();
        g_done = 0u;
    }
}

extern "C" void kernel_launch(void* const* d_in, const int* in_sizes, int n_in,
                              void* d_out, int out_size) {
    const float* x       = (const float*)d_in[0];   // [B, D] f32
    const int*   labels  = (const int*)  d_in[1];   // [B] i32
    const float* centers = (const float*)d_in[2];   // [C, K, D] f32

    hist_kernel<<<256, 256>>>(labels);
    scan_kernel<<<1, 1024>>>();
    scatter_kernel<<<512, 256>>>(labels);
    dist_kernel<<<GRID, 256>>>((const float4*)x, (const float4*)centers, (float*)d_out);
}

// round 9
// speedup vs baseline: 2.0240x; 1.9621x over previous
#include <cuda_runtime.h>
#include <cuda_bf16.h>

// Problem constants (fixed by the reference)
static constexpr int BN = 262144;   // batch (2^18)
static constexpr int KN = 3;        // centers per class
static constexpr int DN = 64;       // feature dim
static constexpr float TH_F  = 0.95f;
static constexpr float EPS_F = 1e-12f;

static constexpr int GRID      = 2048;
static constexpr int ROWS_ITER = 32;                    // rows per block-iteration
static constexpr int ITERS     = BN / (GRID * ROWS_ITER); // 4
static constexpr int F4_ITER   = ROWS_ITER * (DN / 4);  // 512 float4 per stage (8KB)

// Global accumulators (zero-initialized at module load; reset by last block each run)
__device__ double g_sum_min    = 0.0;
__device__ double g_sum_masked = 0.0;
__device__ double g_cnt        = 0.0;
__device__ unsigned int g_done = 0u;

__device__ __forceinline__ void cp_async16(void* smem_dst, const void* gmem_src) {
    unsigned sa = (unsigned)__cvta_generic_to_shared(smem_dst);
    asm volatile("cp.async.cg.shared.global [%0], [%1], 16;\n" :: "r"(sa), "l"(gmem_src));
}
__device__ __forceinline__ void cp_async_commit() {
    asm volatile("cp.async.commit_group;\n" ::: "memory");
}
template <int N>
__device__ __forceinline__ void cp_async_wait() {
    asm volatile("cp.async.wait_group %0;\n" :: "n"(N) : "memory");
}

__device__ __forceinline__ float dist4(const float4 a, const float4 b) {
    const float d0 = a.x - b.x, d1 = a.y - b.y;
    const float d2 = a.z - b.z, d3 = a.w - b.w;
    return d0 * d0 + d1 * d1 + d2 * d2 + d3 * d3;
}

// x is staged global->smem via cp.async (zero register pressure, latency fully
// pipelined). Centers via LDG (L1/L2 resident). 8 lanes/row, 4 rows/warp/iter.
__global__ void __launch_bounds__(256)
dist_kernel(const float4* __restrict__ x4,
            const int*    __restrict__ labels,
            const float4* __restrict__ c4,
            float*        __restrict__ out)
{
    __shared__ float4 xbuf[2][F4_ITER];   // 2 x 8KB
    __shared__ float  sm[3][8];
    __shared__ bool   s_last;

    const int tid   = threadIdx.x;
    const int lane  = tid & 31;
    const int w     = tid >> 5;           // warp in block (0..7)
    const int r     = lane >> 3;          // row within warp group (0..3)
    const int s     = lane & 7;           // float4 slot within 128B half-row
    const int row_local = w * 4 + r;      // 0..31

    // Prefetch all labels for this block's 4 iterations (independent LDGs)
    int labs[ITERS];
    #pragma unroll
    for (int it = 0; it < ITERS; it++) {
        const int base = (blockIdx.x + it * GRID) * ROWS_ITER;
        labs[it] = __ldg(&labels[base + row_local]);
    }

    // Stage 0 fill: 512 float4, 2 per thread
    {
        const float4* xg = x4 + (size_t)blockIdx.x * F4_ITER;
        cp_async16(&xbuf[0][tid],       xg + tid);
        cp_async16(&xbuf[0][tid + 256], xg + tid + 256);
        cp_async_commit();
    }

    float acc_min = 0.f, acc_msk = 0.f, acc_cnt = 0.f;

    #pragma unroll
    for (int it = 0; it < ITERS; it++) {
        // Kick off next stage fill before waiting on current
        if (it + 1 < ITERS) {
            const float4* xg = x4 + (size_t)(blockIdx.x + (it + 1) * GRID) * F4_ITER;
            float4* dst = xbuf[(it + 1) & 1];
            cp_async16(&dst[tid],       xg + tid);
            cp_async16(&dst[tid + 256], xg + tid + 256);
            cp_async_commit();
            cp_async_wait<1>();
        } else {
            cp_async_wait<0>();
        }
        __syncthreads();

        const float4* xs = xbuf[it & 1];
        const float4 xv0 = xs[row_local * 16 + s];
        const float4 xv1 = xs[row_local * 16 + s + 8];

        const float4* cb = c4 + (size_t)labs[it] * (KN * (DN / 4)) + s;

        // 3 centers x 2 half-rows; warp LDG covers 4 full 128B lines
        const float4 c00 = __ldg(cb + 0);
        const float4 c01 = __ldg(cb + 8);
        const float4 c10 = __ldg(cb + 16);
        const float4 c11 = __ldg(cb + 24);
        const float4 c20 = __ldg(cb + 32);
        const float4 c21 = __ldg(cb + 40);

        float p0 = dist4(xv0, c00) + dist4(xv1, c01);
        float p1 = dist4(xv0, c10) + dist4(xv1, c11);
        float p2 = dist4(xv0, c20) + dist4(xv1, c21);

        // Reduce within the 8-lane group (xor 1,2,4 never crosses groups)
        #pragma unroll
        for (int o = 1; o < 8; o <<= 1) {
            p0 += __shfl_xor_sync(0xffffffffu, p0, o);
            p1 += __shfl_xor_sync(0xffffffffu, p1, o);
            p2 += __shfl_xor_sync(0xffffffffu, p2, o);
        }

        if (s == 0) {
            const float mn  = fminf(fminf(p0, p1), p2);
            const float mx  = fmaxf(fmaxf(p0, p1), p2);
            const float mid = (p0 + p1 + p2) - mn - mx;

            const float a = mn  + EPS_F;
            const float b = mid + EPS_F;
            const float p = a / (a + b);                  // 0 < p <= 0.5
            const float ent = -(p * log2f(p) + (1.f - p) * log2f(1.f - p));

            acc_min += mn;
            if (ent <= TH_F) { acc_msk += mn; acc_cnt += 1.f; }
        }

        // Guard buffer reuse: next iteration's fill overwrites stage (it+1)&1,
        // wait, it writes (it+2)&1 == it&1 which we just finished reading.
        __syncthreads();
    }

    // Warp reduce (only s==0 lanes carry nonzero values)
    #pragma unroll
    for (int o = 16; o > 0; o >>= 1) {
        acc_min += __shfl_xor_sync(0xffffffffu, acc_min, o);
        acc_msk += __shfl_xor_sync(0xffffffffu, acc_msk, o);
        acc_cnt += __shfl_xor_sync(0xffffffffu, acc_cnt, o);
    }

    if (lane == 0) { sm[0][w] = acc_min; sm[1][w] = acc_msk; sm[2][w] = acc_cnt; }
    __syncthreads();

    if (tid == 0) {
        float a = 0.f, b = 0.f, c = 0.f;
        #pragma unroll
        for (int i = 0; i < 8; i++) { a += sm[0][i]; b += sm[1][i]; c += sm[2][i]; }
        atomicAdd(&g_sum_min,    (double)a);
        atomicAdd(&g_sum_masked, (double)b);
        atomicAdd(&g_cnt,        (double)c);
        __threadfence();
        const unsigned int ticket = atomicAdd(&g_done, 1u);
        s_last = (ticket == (unsigned int)(GRID - 1));
    }
    __syncthreads();

    // Last block: produce outputs and reset state for the next graph replay
    if (s_last && tid == 0) {
        __threadfence();
        const double smn = g_sum_min;
        const double smk = g_sum_masked;
        const double cnt = g_cnt;
        out[0] = (float)(smn / (double)BN);
        out[1] = (float)(smk / cnt);
        g_sum_min = 0.0; g_sum_masked = 0.0; g_cnt = 0.0;
        __threadfence();
        g_done = 0u;
    }
}

extern "C" void kernel_launch(void* const* d_in, const int* in_sizes, int n_in,
                              void* d_out, int out_size) {
    const float* x       = (const float*)d_in[0];   // [B, D] f32
    const int*   labels  = (const int*)  d_in[1];   // [B] i32
    const float* centers = (const float*)d_in[2];   // [C, K, D] f32

    dist_kernel<<<GRID, 256>>>((const float4*)x, labels,
                               (const float4*)centers, (float*)d_out);
}